// round 16
// baseline (speedup 1.0000x reference)
#include <cuda_runtime.h>

// ---------------------------------------------------------------------------
// GAT layer (GATConv + Linear + ReLU), fp32 — padded buckets, half-warp GEMMs.
//
// vs R15 (108.3us):
//  * k56: degrees prefetched (1 coalesced LDG + shfl, was 8 serialized
//    uniform loads); slot staging software-pipelined one round ahead
//    (hides ~250cyc slot fetch under the gather loop).
//  * ss rows padded to 34 -> slot pairs read as ONE LDS.128.
//  * xs/rs rows padded to HID+4: kills the 2-way bank conflict on every
//    GEMM broadcast (halves were 1024B apart = same bank).
// 4 launches: setup -> K1 -> K4 -> K56.
// ---------------------------------------------------------------------------

#define MAX_N 100000
#define MAX_E 1000000
#define HID 64
#define HIDP (HID + 4)    // padded row: 272B stride, bank-conflict-free, 16B-aligned
#define PAD 64            // slots per node (Poisson(10) tail ~ 0; guarded)
#define NEG_SLOPE 0.2f
#define NBLK 1184         // 8 blocks/SM on 148 SMs

__device__ __align__(16) float g_h[(size_t)MAX_N * HID];   // projected feats
__device__ float g_asrc[MAX_N];
__device__ float g_adst[MAX_N];
__device__ float g_vdst[HID];
__device__ int   g_is64;
__device__ int   g_cur[MAX_N];                              // cursor = degree
__device__ __align__(16) int2 g_slot[(size_t)MAX_N * PAD];  // (src, bitcast w)

// --------------------------- S: setup = probe + v_dst ------------------------
__global__ void k_setup(const float* __restrict__ W_dst,
                        const float* __restrict__ att_dst,
                        const int* __restrict__ ei32) {
    int t = threadIdx.x;
    if (t < HID) {
        float acc = 0.f;
#pragma unroll
        for (int j = 0; j < HID; j++) acc += W_dst[t * HID + j] * att_dst[j];
        g_vdst[t] = acc;
    } else if (t == HID) {
        int nz = 0;
#pragma unroll
        for (int i = 1; i < 128; i += 2) nz += (ei32[i] != 0);
        g_is64 = (nz == 0) ? 1 : 0;   // int64 little-endian small ids
    }
}

// --------------------------- K1: projection (half-warp x4) + scores ----------
__global__ void k1_proj(const float* __restrict__ x,
                        const float* __restrict__ W_src,
                        const float* __restrict__ att_src,
                        int N) {
    __shared__ float Ws[HID * HID];
    __shared__ float xs[8][8][HIDP];         // padded rows: no bank conflicts
    for (int i = threadIdx.x; i < HID * HID; i += blockDim.x) Ws[i] = W_src[i];
    __syncthreads();

    const int lane = threadIdx.x & 31;
    const int warp = threadIdx.x >> 5;
    const int half = lane >> 4;
    const int c    = lane & 15;
    const float4 av = ((const float4*)att_src)[c];
    const float4 vv = ((const float4*)g_vdst)[c];
    const int ngroups = (N + 7) / 8;

    for (int g = blockIdx.x * 8 + warp; g < ngroups; g += gridDim.x * 8) {
        const int n0  = g * 8;
        const int cnt = (N - n0 < 8) ? (N - n0) : 8;

        float4 xv[4];
#pragma unroll
        for (int m = 0; m < 4; m++) {
            const int mi = half * 4 + m;
            xv[m] = (mi < cnt)
                ? __ldg((const float4*)(x + (size_t)(n0 + mi) * HID) + c)
                : make_float4(0.f, 0.f, 0.f, 0.f);
            ((float4*)xs[warp][mi])[c] = xv[m];
        }
        __syncwarp();

        float4 acc[4];
#pragma unroll
        for (int m = 0; m < 4; m++) acc[m] = make_float4(0.f, 0.f, 0.f, 0.f);

#pragma unroll
        for (int k = 0; k < HID; k++) {
            const float4 wv = ((const float4*)(Ws + k * HID))[c];
#pragma unroll
            for (int m = 0; m < 4; m++) {
                const float xk = xs[warp][half * 4 + m][k];   // LDS broadcast
                acc[m].x = fmaf(xk, wv.x, acc[m].x);
                acc[m].y = fmaf(xk, wv.y, acc[m].y);
                acc[m].z = fmaf(xk, wv.z, acc[m].z);
                acc[m].w = fmaf(xk, wv.w, acc[m].w);
            }
        }

#pragma unroll
        for (int m = 0; m < 4; m++) {
            const int mi = half * 4 + m;
            if (mi >= cnt) break;
            const int n = n0 + mi;
            ((float4*)(g_h + (size_t)n * HID))[c] = acc[m];

            float ps = acc[m].x * av.x + acc[m].y * av.y +
                       acc[m].z * av.z + acc[m].w * av.w;
            float pd = xv[m].x * vv.x + xv[m].y * vv.y +
                       xv[m].z * vv.z + xv[m].w * vv.w;
#pragma unroll
            for (int o = 8; o > 0; o >>= 1) {       // reduce within half-warp
                ps += __shfl_xor_sync(0xffffffffu, ps, o);
                pd += __shfl_xor_sync(0xffffffffu, pd, o);
            }
            if (c == 0) {
                g_asrc[n] = ps;
                g_adst[n] = pd;
                g_cur[n]  = 0;
            }
        }
        __syncwarp();   // xs reuse guard
    }
}

// --------------------------- K4: edge scatter, 4 edges/thread ----------------
__global__ void k4_scatter(const void* __restrict__ ei, long long E) {
    const long long base = ((long long)blockIdx.x * blockDim.x + threadIdx.x) * 4;
    if (base >= E) return;
    const int is64 = g_is64;

    int s[4], t[4];
    if (!is64 && base + 3 < E) {               // fast path: vector loads
        const int4 s4 = __ldg((const int4*)((const int*)ei + base));
        const int4 t4 = __ldg((const int4*)((const int*)ei + E + base));
        s[0] = s4.x; s[1] = s4.y; s[2] = s4.z; s[3] = s4.w;
        t[0] = t4.x; t[1] = t4.y; t[2] = t4.z; t[3] = t4.w;
    } else {
#pragma unroll
        for (int m = 0; m < 4; m++) {
            const long long i = base + m;
            if (i < E) {
                if (is64) {
                    s[m] = (int)((const long long*)ei)[i];
                    t[m] = (int)((const long long*)ei)[E + i];
                } else {
                    s[m] = ((const int*)ei)[i];
                    t[m] = ((const int*)ei)[E + i];
                }
            } else { s[m] = -1; t[m] = 0; }
        }
    }

    float w[4];
#pragma unroll
    for (int m = 0; m < 4; m++) {
        if (s[m] < 0) continue;
        float e = __ldg(&g_asrc[s[m]]) + __ldg(&g_adst[t[m]]);
        e = (e > 0.f) ? e : NEG_SLOPE * e;
        w[m] = __expf(e);
    }
#pragma unroll
    for (int m = 0; m < 4; m++) {
        if (s[m] < 0) continue;
        const int c = atomicAdd(&g_cur[t[m]], 1);
        if (c < PAD)
            g_slot[(size_t)t[m] * PAD + c] = make_int2(s[m], __float_as_int(w[m]));
    }
}

// --------------------------- K56: aggregate + output GEMM (fused) ------------
// Aggregation pipelined: degrees prefetched once per group; round m2+1's
// slot rows fetched while round m2's gather loop runs. Slot pairs read as
// int4 (LDS.128). GEMM: half-warp x 4 nodes, float4 columns, padded rs.
__global__ void k56_agg_out(const float* __restrict__ bias,
                            const float* __restrict__ W_lin,
                            const float* __restrict__ b_lin,
                            float* __restrict__ out, int N) {
    __shared__ float Ws[HID * HID];
    __shared__ float rs[8][8][HIDP];
    __shared__ __align__(16) int2 ss[8][2][34];  // 34: int4-aligned, padded
    for (int i = threadIdx.x; i < HID * HID; i += blockDim.x) Ws[i] = W_lin[i];
    __syncthreads();

    const int lane = threadIdx.x & 31;
    const int warp = threadIdx.x >> 5;
    const int half = lane >> 4;
    const int c    = lane & 15;
    const float4 bi = ((const float4*)bias)[c];
    const float4 bl = ((const float4*)b_lin)[c];
    const int ngroups = (N + 7) / 8;

    for (int g = blockIdx.x * 8 + warp; g < ngroups; g += gridDim.x * 8) {
        const int n0  = g * 8;
        const int cnt = (N - n0 < 8) ? (N - n0) : 8;

        // prefetch all 8 degrees: one coalesced load + shfl distribution
        int dreg = 0;
        if (lane < 8 && lane < cnt) dreg = g_cur[n0 + lane];

        // prefetch round 0 slot rows
        int dA = __shfl_sync(0xffffffffu, dreg, 0); dA = (dA < PAD) ? dA : PAD;
        int dB = __shfl_sync(0xffffffffu, dreg, 1); dB = (dB < PAD) ? dB : PAD;
        int2 stA = (lane < ((dA < 32) ? dA : 32))
            ? __ldg(g_slot + (size_t)n0 * PAD + lane) : make_int2(0, 0);
        int2 stB = (lane < ((dB < 32) ? dB : 32))
            ? __ldg(g_slot + (size_t)(n0 + 1) * PAD + lane) : make_int2(0, 0);

        for (int m2 = 0; m2 < 4; m2++) {
            // stage current round (prefetched last round)
            ss[warp][0][lane] = stA;
            ss[warp][1][lane] = stB;
            __syncwarp();

            const int cdA = dA, cdB = dB;
            const int2* cslA = g_slot + (size_t)(n0 + 2 * m2) * PAD;
            const int2* cslB = cslA + PAD;

            // issue next round's prefetch before processing (overlap)
            if (m2 < 3) {
                dA = __shfl_sync(0xffffffffu, dreg, 2 * m2 + 2);
                dA = (dA < PAD) ? dA : PAD;
                dB = __shfl_sync(0xffffffffu, dreg, 2 * m2 + 3);
                dB = (dB < PAD) ? dB : PAD;
                const int2* nsl = g_slot + (size_t)(n0 + 2 * m2 + 2) * PAD;
                stA = (lane < ((dA < 32) ? dA : 32)) ? __ldg(nsl + lane)
                                                     : make_int2(0, 0);
                stB = (lane < ((dB < 32) ? dB : 32)) ? __ldg(nsl + PAD + lane)
                                                     : make_int2(0, 0);
            }

            // gather loop: 2 edges per iter via one LDS.128
            const int dA32 = (cdA < 32) ? cdA : 32;
            const int dB32 = (cdB < 32) ? cdB : 32;
            const int dmax = (dA32 > dB32) ? dA32 : dB32;
            const int iters = (dmax + 1) >> 1;
            const int4* myss4 = (const int4*)ss[warp][half];

            float denom = 0.f;
            float4 acc = make_float4(0.f, 0.f, 0.f, 0.f);
            for (int i = 0; i < iters; i++) {
                const int4 pp = myss4[i];             // 2 slots, LDS.128
                const float w0 = __int_as_float(pp.y);
                const float w1 = __int_as_float(pp.w);
                const float4 h0 =
                    __ldg((const float4*)(g_h + (size_t)pp.x * HID) + c);
                const float4 h1 =
                    __ldg((const float4*)(g_h + (size_t)pp.z * HID) + c);
                denom += w0 + w1;
                acc.x = fmaf(w0, h0.x, fmaf(w1, h1.x, acc.x));
                acc.y = fmaf(w0, h0.y, fmaf(w1, h1.y, acc.y));
                acc.z = fmaf(w0, h0.z, fmaf(w1, h1.z, acc.z));
                acc.w = fmaf(w0, h0.w, fmaf(w1, h1.w, acc.w));
            }

            // rare tail: this half's node has deg > 32
            const int mydeg = half ? cdB : cdA;
            const int2* mysl = half ? cslB : cslA;
            for (int j = 32; j < mydeg; j++) {
                const int2 p = __ldg(mysl + j);
                const float w = __uint_as_float((unsigned)p.y);
                denom += w;
                const float4 hv =
                    __ldg((const float4*)(g_h + (size_t)p.x * HID) + c);
                acc.x = fmaf(w, hv.x, acc.x);
                acc.y = fmaf(w, hv.y, acc.y);
                acc.z = fmaf(w, hv.z, acc.z);
                acc.w = fmaf(w, hv.w, acc.w);
            }

            if (2 * m2 + half < cnt) {
                const float inv = 1.f / (denom + 1e-16f);
                ((float4*)rs[warp][2 * m2 + half])[c] =
                    make_float4(acc.x * inv + bi.x, acc.y * inv + bi.y,
                                acc.z * inv + bi.z, acc.w * inv + bi.w);
            }
            __syncwarp();   // ss reuse guard
        }

        // ---- output GEMM: half-warp x 4 nodes, float4 columns ----
        float4 oacc[4];
#pragma unroll
        for (int m = 0; m < 4; m++) oacc[m] = make_float4(0.f, 0.f, 0.f, 0.f);

#pragma unroll
        for (int k = 0; k < HID; k++) {
            const float4 wv = ((const float4*)(Ws + k * HID))[c];
#pragma unroll
            for (int m = 0; m < 4; m++) {
                const float rk = rs[warp][half * 4 + m][k];   // LDS broadcast
                oacc[m].x = fmaf(rk, wv.x, oacc[m].x);
                oacc[m].y = fmaf(rk, wv.y, oacc[m].y);
                oacc[m].z = fmaf(rk, wv.z, oacc[m].z);
                oacc[m].w = fmaf(rk, wv.w, oacc[m].w);
            }
        }

#pragma unroll
        for (int m = 0; m < 4; m++) {
            const int mi = half * 4 + m;
            if (mi >= cnt) break;
            float4 o;
            o.x = fmaxf(oacc[m].x + bl.x, 0.f);
            o.y = fmaxf(oacc[m].y + bl.y, 0.f);
            o.z = fmaxf(oacc[m].z + bl.z, 0.f);
            o.w = fmaxf(oacc[m].w + bl.w, 0.f);
            ((float4*)(out + (size_t)(n0 + mi) * HID))[c] = o;
        }
        __syncwarp();   // rs reuse guard
    }
}

// ---------------------------------------------------------------------------
extern "C" void kernel_launch(void* const* d_in, const int* in_sizes, int n_in,
                              void* d_out, int out_size) {
    const float* x       = (const float*)d_in[0];
    const void*  ei      = d_in[1];                 // int32 or int64, probed
    const float* W_src   = (const float*)d_in[2];
    const float* W_dst   = (const float*)d_in[3];
    const float* att_src = (const float*)d_in[4];
    const float* att_dst = (const float*)d_in[5];
    const float* bias    = (const float*)d_in[6];
    const float* W_lin   = (const float*)d_in[7];
    const float* b_lin   = (const float*)d_in[8];
    float*       out     = (float*)d_out;

    const int       N = in_sizes[0] / HID;
    const long long E = in_sizes[1] / 2;
    const int       ngroups = (N + 7) / 8;
    const int       nbg = (ngroups + 7) / 8 < NBLK ? (ngroups + 7) / 8 : NBLK;
    const long long nthr4 = (E + 3) / 4;

    k_setup<<<1, 128>>>(W_dst, att_dst, (const int*)ei);
    k1_proj<<<nbg, 256>>>(x, W_src, att_src, N);
    k4_scatter<<<(int)((nthr4 + 255) / 256), 256>>>(ei, E);
    k56_agg_out<<<nbg, 256>>>(bias, W_lin, b_lin, out, N);
}